// round 1
// baseline (speedup 1.0000x reference)
#include <cuda_runtime.h>

// GNNSurrogate: fully fused per-sample GNN.
// x:[16384,128,3] adj:[128,128] W_lift:[3,32] b_lift:[32]
// W1/W2:[3,32,32] b1/b2:[3,32] W_ro:[32] b_ro:[1] -> out:[16384]
//
// Block = 512 threads = 4 groups of 128; each group handles one sample,
// thread t owns node row i = t&127. All weights + padded adjacency in SMEM.
// All matmuls done with packed f32x2 FMAs (2x fp32 FFMA throughput on sm_103a).

#define THREADS 512
#define GROUPS 4

// shared-memory float offsets
#define ADJ_OFF 0
#define ADJ_SZ  (128 * 129)          // padded stride 129: conflict-free adj[i*129+j]
#define WL_OFF  (ADJ_OFF + ADJ_SZ)   // 16512
#define BL_OFF  (WL_OFF + 96)
#define W1_OFF  (BL_OFF + 32)
#define B1_OFF  (W1_OFF + 3072)
#define W2_OFF  (B1_OFF + 96)
#define B2_OFF  (W2_OFF + 3072)
#define WRO_OFF (B2_OFF + 96)
#define RED_OFF (WRO_OFF + 32)       // 16 floats (per-warp partial sums)
#define LOC_OFF (RED_OFF + 16)       // 23024 -> byte offset 92096, 16B aligned
#define SMEM_FLOATS (LOC_OFF + GROUPS * 128 * 32)   // 39408 floats = 157632 B

typedef unsigned long long u64;

__device__ __forceinline__ u64 f2pack(float lo, float hi) {
    u64 r;
    asm("mov.b64 %0, {%1, %2};" : "=l"(r) : "f"(lo), "f"(hi));
    return r;
}
__device__ __forceinline__ void f2unpack(u64 v, float& lo, float& hi) {
    asm("mov.b64 {%0, %1}, %2;" : "=f"(lo), "=f"(hi) : "l"(v));
}
__device__ __forceinline__ u64 ffma2(u64 a, u64 b, u64 c) {
    u64 d;
    asm("fma.rn.f32x2 %0, %1, %2, %3;" : "=l"(d) : "l"(a), "l"(b), "l"(c));
    return d;
}

__global__ void __launch_bounds__(THREADS, 1) gnn_fused_kernel(
    const float* __restrict__ x, const float* __restrict__ adj,
    const float* __restrict__ W_lift, const float* __restrict__ b_lift,
    const float* __restrict__ W1, const float* __restrict__ b1,
    const float* __restrict__ W2, const float* __restrict__ b2,
    const float* __restrict__ W_ro, const float* __restrict__ b_ro,
    float* __restrict__ out)
{
    extern __shared__ float sm[];
    const int tid = threadIdx.x;

    // ---- stage adjacency (padded) + all weights into SMEM ----
    for (int idx = tid; idx < 128 * 128; idx += THREADS)
        sm[ADJ_OFF + (idx >> 7) * 129 + (idx & 127)] = adj[idx];
    for (int idx = tid; idx < 96; idx += THREADS)  sm[WL_OFF + idx] = W_lift[idx];
    if (tid < 32)                                  sm[BL_OFF + tid] = b_lift[tid];
    for (int idx = tid; idx < 3072; idx += THREADS) sm[W1_OFF + idx] = W1[idx];
    for (int idx = tid; idx < 96; idx += THREADS)  sm[B1_OFF + idx] = b1[idx];
    for (int idx = tid; idx < 3072; idx += THREADS) sm[W2_OFF + idx] = W2[idx];
    for (int idx = tid; idx < 96; idx += THREADS)  sm[B2_OFF + idx] = b2[idx];
    if (tid < 32)                                  sm[WRO_OFF + tid] = W_ro[tid];
    __syncthreads();

    const int g = tid >> 7;          // sample group 0..3
    const int i = tid & 127;         // node row
    const int b = blockIdx.x * GROUPS + g;

    // ---- lift: h = x @ W_lift + b_lift ----
    float h[32];
    {
        const float* xp = x + ((size_t)b * 128 + i) * 3;
        float x0 = xp[0], x1 = xp[1], x2 = xp[2];
        #pragma unroll
        for (int j = 0; j < 32; j++)
            h[j] = fmaf(x0, sm[WL_OFF + j],
                   fmaf(x1, sm[WL_OFF + 32 + j],
                   fmaf(x2, sm[WL_OFF + 64 + j], sm[BL_OFF + j])));
    }

    float* loc = sm + LOC_OFF + g * 4096;   // this group's [128,32] local tile

    for (int l = 0; l < 3; l++) {
        // ---- matmul1 + relu: t = relu(h @ W1[l] + b1[l]) ----
        u64 t2[16];
        {
            const u64* bp = (const u64*)(sm + B1_OFF + l * 32);
            #pragma unroll
            for (int q = 0; q < 16; q++) t2[q] = bp[q];
            const ulonglong2* w = (const ulonglong2*)(sm + W1_OFF + l * 1024);
            #pragma unroll
            for (int k = 0; k < 32; k++) {
                u64 hk = f2pack(h[k], h[k]);
                #pragma unroll
                for (int q = 0; q < 8; q++) {
                    ulonglong2 p = w[k * 8 + q];
                    t2[2 * q]     = ffma2(hk, p.x, t2[2 * q]);
                    t2[2 * q + 1] = ffma2(hk, p.y, t2[2 * q + 1]);
                }
            }
        }
        float t[32];
        #pragma unroll
        for (int q = 0; q < 16; q++) {
            float lo, hi;
            f2unpack(t2[q], lo, hi);
            t[2 * q]     = fmaxf(lo, 0.f);
            t[2 * q + 1] = fmaxf(hi, 0.f);
        }

        // ---- matmul2: v = t @ W2[l] + b2[l] ----
        u64 v2[16];
        {
            const u64* bp = (const u64*)(sm + B2_OFF + l * 32);
            #pragma unroll
            for (int q = 0; q < 16; q++) v2[q] = bp[q];
            const ulonglong2* w = (const ulonglong2*)(sm + W2_OFF + l * 1024);
            #pragma unroll
            for (int k = 0; k < 32; k++) {
                u64 tk = f2pack(t[k], t[k]);
                #pragma unroll
                for (int q = 0; q < 8; q++) {
                    ulonglong2 p = w[k * 8 + q];
                    v2[2 * q]     = ffma2(tk, p.x, v2[2 * q]);
                    v2[2 * q + 1] = ffma2(tk, p.y, v2[2 * q + 1]);
                }
            }
        }

        // write this node's local row to SMEM
        {
            ulonglong2* lrow = (ulonglong2*)(loc + i * 32);
            #pragma unroll
            for (int q = 0; q < 8; q++) {
                ulonglong2 p;
                p.x = v2[2 * q];
                p.y = v2[2 * q + 1];
                lrow[q] = p;
            }
        }
        __syncthreads();

        // ---- aggregation: h_new[i,:] = sum_j adj[i,j] * local[j,:] ----
        u64 acc[16];
        #pragma unroll
        for (int q = 0; q < 16; q++) acc[q] = 0ULL;   // bit pattern {0.f,0.f}
        const float* arow = sm + ADJ_OFF + i * 129;
        const ulonglong2* Lb = (const ulonglong2*)loc;
        #pragma unroll 4
        for (int j = 0; j < 128; j++) {
            float a = arow[j];                 // conflict-free (pad 129)
            u64 a2 = f2pack(a, a);
            #pragma unroll
            for (int q = 0; q < 8; q++) {
                ulonglong2 p = Lb[j * 8 + q];  // broadcast LDS.128
                acc[2 * q]     = ffma2(a2, p.x, acc[2 * q]);
                acc[2 * q + 1] = ffma2(a2, p.y, acc[2 * q + 1]);
            }
        }
        #pragma unroll
        for (int q = 0; q < 16; q++)
            f2unpack(acc[q], h[2 * q], h[2 * q + 1]);
        __syncthreads();   // protect local tile before next layer's writes
    }

    // ---- readout: out[b] = mean_i(h) @ W_ro + b_ro ----
    float s = 0.f;
    #pragma unroll
    for (int c = 0; c < 32; c++) s = fmaf(h[c], sm[WRO_OFF + c], s);
    #pragma unroll
    for (int o = 16; o > 0; o >>= 1) s += __shfl_xor_sync(0xffffffffu, s, o);
    const int w = tid >> 5;
    if ((tid & 31) == 0) sm[RED_OFF + w] = s;
    __syncthreads();
    if (i == 0) {
        float tot = sm[RED_OFF + g * 4] + sm[RED_OFF + g * 4 + 1] +
                    sm[RED_OFF + g * 4 + 2] + sm[RED_OFF + g * 4 + 3];
        out[b] = fmaf(tot, 1.f / 128.f, b_ro[0]);
    }
}

extern "C" void kernel_launch(void* const* d_in, const int* in_sizes, int n_in,
                              void* d_out, int out_size)
{
    const float* x      = (const float*)d_in[0];
    const float* adj    = (const float*)d_in[1];
    const float* W_lift = (const float*)d_in[2];
    const float* b_lift = (const float*)d_in[3];
    const float* W1     = (const float*)d_in[4];
    const float* b1     = (const float*)d_in[5];
    const float* W2     = (const float*)d_in[6];
    const float* b2     = (const float*)d_in[7];
    const float* W_ro   = (const float*)d_in[8];
    const float* b_ro   = (const float*)d_in[9];
    float* out = (float*)d_out;

    const size_t smem_bytes = SMEM_FLOATS * sizeof(float);
    cudaFuncSetAttribute(gnn_fused_kernel,
                         cudaFuncAttributeMaxDynamicSharedMemorySize,
                         (int)smem_bytes);

    const int batch = 16384;
    gnn_fused_kernel<<<batch / GROUPS, THREADS, smem_bytes>>>(
        x, adj, W_lift, b_lift, W1, b1, W2, b2, W_ro, b_ro, out);
}

// round 9
// speedup vs baseline: 1.2536x; 1.2536x over previous
#include <cuda_runtime.h>

// GNNSurrogate fully fused, r=2 node blocking.
// 256 threads/block = 4 samples x 64 threads; each thread owns node rows
// i and i+64 of its sample. All shared loads (MLP weights, agg local rows)
// are amortized over both rows -> LDS traffic ~halved vs r=1.
// Block-wide __syncthreads() only (named per-group barriers removed: they are
// the one construct delta vs the last known-passing kernel across 3 failed runs).

#define THREADS 256
#define GROUPS 4

// shared-memory float offsets
#define ADJ_OFF 0
#define ADJ_SZ  (128 * 129)          // padded stride 129: conflict-free column reads
#define WL_OFF  (ADJ_OFF + ADJ_SZ)
#define BL_OFF  (WL_OFF + 96)
#define W1_OFF  (BL_OFF + 32)
#define B1_OFF  (W1_OFF + 3072)
#define W2_OFF  (B1_OFF + 96)
#define B2_OFF  (W2_OFF + 3072)
#define WRO_OFF (B2_OFF + 96)
#define RED_OFF (WRO_OFF + 32)       // 8 floats (per-warp partials)
#define LOC_OFF (RED_OFF + 16)       // keep 16B alignment
#define SMEM_FLOATS (LOC_OFF + GROUPS * 128 * 32)

typedef unsigned long long u64;

__device__ __forceinline__ u64 f2pack(float lo, float hi) {
    u64 r;
    asm("mov.b64 %0, {%1, %2};" : "=l"(r) : "f"(lo), "f"(hi));
    return r;
}
__device__ __forceinline__ void f2unpack(u64 v, float& lo, float& hi) {
    asm("mov.b64 {%0, %1}, %2;" : "=f"(lo), "=f"(hi) : "l"(v));
}
__device__ __forceinline__ u64 ffma2(u64 a, u64 b, u64 c) {
    u64 d;
    asm("fma.rn.f32x2 %0, %1, %2, %3;" : "=l"(d) : "l"(a), "l"(b), "l"(c));
    return d;
}

// one 32->32 matmul step applied to two rows, weights broadcast from smem
__device__ __forceinline__ void mm2(const float* __restrict__ wbase,
                                    const float* __restrict__ bias,
                                    const float* ha, const float* hb,
                                    u64* ta, u64* tb)
{
    const u64* bp = (const u64*)bias;
    #pragma unroll
    for (int q = 0; q < 16; q++) { ta[q] = bp[q]; tb[q] = bp[q]; }
    const ulonglong2* w = (const ulonglong2*)wbase;
    #pragma unroll 4
    for (int k = 0; k < 32; k++) {
        u64 ak = f2pack(ha[k], ha[k]);
        u64 bk = f2pack(hb[k], hb[k]);
        #pragma unroll
        for (int q = 0; q < 8; q++) {
            ulonglong2 p = w[k * 8 + q];
            ta[2 * q]     = ffma2(ak, p.x, ta[2 * q]);
            ta[2 * q + 1] = ffma2(ak, p.y, ta[2 * q + 1]);
            tb[2 * q]     = ffma2(bk, p.x, tb[2 * q]);
            tb[2 * q + 1] = ffma2(bk, p.y, tb[2 * q + 1]);
        }
    }
}

__global__ void __launch_bounds__(THREADS, 1) gnn_fused_kernel(
    const float* __restrict__ x, const float* __restrict__ adj,
    const float* __restrict__ W_lift, const float* __restrict__ b_lift,
    const float* __restrict__ W1, const float* __restrict__ b1,
    const float* __restrict__ W2, const float* __restrict__ b2,
    const float* __restrict__ W_ro, const float* __restrict__ b_ro,
    float* __restrict__ out)
{
    extern __shared__ float sm[];
    const int tid = threadIdx.x;

    // ---- stage adjacency (padded) + weights ----
    for (int idx = tid; idx < 128 * 128; idx += THREADS)
        sm[ADJ_OFF + (idx >> 7) * 129 + (idx & 127)] = adj[idx];
    for (int idx = tid; idx < 96; idx += THREADS)   sm[WL_OFF + idx] = W_lift[idx];
    if (tid < 32)                                   sm[BL_OFF + tid] = b_lift[tid];
    for (int idx = tid; idx < 3072; idx += THREADS) sm[W1_OFF + idx] = W1[idx];
    for (int idx = tid; idx < 96; idx += THREADS)   sm[B1_OFF + idx] = b1[idx];
    for (int idx = tid; idx < 3072; idx += THREADS) sm[W2_OFF + idx] = W2[idx];
    for (int idx = tid; idx < 96; idx += THREADS)   sm[B2_OFF + idx] = b2[idx];
    if (tid < 32)                                   sm[WRO_OFF + tid] = W_ro[tid];
    __syncthreads();

    const int g  = tid >> 6;          // sample group 0..3
    const int i0 = tid & 63;          // first node row
    const int i1 = i0 + 64;           // second node row
    const int b  = blockIdx.x * GROUPS + g;

    // ---- lift for both rows ----
    float ha[32], hb[32];
    {
        const float* xa = x + ((size_t)b * 128 + i0) * 3;
        const float* xb = x + ((size_t)b * 128 + i1) * 3;
        float a0 = xa[0], a1 = xa[1], a2 = xa[2];
        float c0 = xb[0], c1 = xb[1], c2 = xb[2];
        #pragma unroll
        for (int j = 0; j < 32; j++) {
            float w0 = sm[WL_OFF + j], w1v = sm[WL_OFF + 32 + j],
                  w2v = sm[WL_OFF + 64 + j], bl = sm[BL_OFF + j];
            ha[j] = fmaf(a0, w0, fmaf(a1, w1v, fmaf(a2, w2v, bl)));
            hb[j] = fmaf(c0, w0, fmaf(c1, w1v, fmaf(c2, w2v, bl)));
        }
    }

    float* loc = sm + LOC_OFF + g * 4096;

    for (int l = 0; l < 3; l++) {
        // ---- matmul1 + relu ----
        u64 ta[16], tb[16];
        mm2(sm + W1_OFF + l * 1024, sm + B1_OFF + l * 32, ha, hb, ta, tb);
        #pragma unroll
        for (int q = 0; q < 16; q++) {
            float lo, hi;
            f2unpack(ta[q], lo, hi);
            ha[2 * q] = fmaxf(lo, 0.f); ha[2 * q + 1] = fmaxf(hi, 0.f);
            f2unpack(tb[q], lo, hi);
            hb[2 * q] = fmaxf(lo, 0.f); hb[2 * q + 1] = fmaxf(hi, 0.f);
        }

        // ---- matmul2 ----
        u64 va[16], vb[16];
        mm2(sm + W2_OFF + l * 1024, sm + B2_OFF + l * 32, ha, hb, va, vb);

        // ---- write local rows ----
        {
            ulonglong2* ra = (ulonglong2*)(loc + i0 * 32);
            ulonglong2* rb = (ulonglong2*)(loc + i1 * 32);
            #pragma unroll
            for (int q = 0; q < 8; q++) {
                ulonglong2 pa; pa.x = va[2 * q]; pa.y = va[2 * q + 1];
                ulonglong2 pb; pb.x = vb[2 * q]; pb.y = vb[2 * q + 1];
                ra[q] = pa; rb[q] = pb;
            }
        }
        __syncthreads();

        // ---- aggregation: both rows share each local[j] load ----
        u64 aa[16], ab[16];
        #pragma unroll
        for (int q = 0; q < 16; q++) { aa[q] = 0ULL; ab[q] = 0ULL; }
        const float* arowa = sm + ADJ_OFF + i0 * 129;
        const float* arowb = sm + ADJ_OFF + i1 * 129;
        const ulonglong2* Lb = (const ulonglong2*)loc;
        #pragma unroll 2
        for (int j = 0; j < 128; j++) {
            u64 ca = f2pack(arowa[j], arowa[j]);
            u64 cb = f2pack(arowb[j], arowb[j]);
            #pragma unroll
            for (int q = 0; q < 8; q++) {
                ulonglong2 p = Lb[j * 8 + q];      // broadcast LDS.128
                aa[2 * q]     = ffma2(ca, p.x, aa[2 * q]);
                aa[2 * q + 1] = ffma2(ca, p.y, aa[2 * q + 1]);
                ab[2 * q]     = ffma2(cb, p.x, ab[2 * q]);
                ab[2 * q + 1] = ffma2(cb, p.y, ab[2 * q + 1]);
            }
        }
        #pragma unroll
        for (int q = 0; q < 16; q++) {
            f2unpack(aa[q], ha[2 * q], ha[2 * q + 1]);
            f2unpack(ab[q], hb[2 * q], hb[2 * q + 1]);
        }
        __syncthreads();   // protect local tile before next layer's writes
    }

    // ---- readout ----
    float s = 0.f;
    #pragma unroll
    for (int c = 0; c < 32; c++) {
        float w = sm[WRO_OFF + c];
        s = fmaf(ha[c], w, s);
        s = fmaf(hb[c], w, s);
    }
    #pragma unroll
    for (int o = 16; o > 0; o >>= 1) s += __shfl_xor_sync(0xffffffffu, s, o);
    const int w = tid >> 5;
    if ((tid & 31) == 0) sm[RED_OFF + w] = s;
    __syncthreads();
    if (i0 == 0) {
        float tot = sm[RED_OFF + 2 * g] + sm[RED_OFF + 2 * g + 1];
        out[b] = fmaf(tot, 1.f / 128.f, b_ro[0]);
    }
}

extern "C" void kernel_launch(void* const* d_in, const int* in_sizes, int n_in,
                              void* d_out, int out_size)
{
    const float* x      = (const float*)d_in[0];
    const float* adj    = (const float*)d_in[1];
    const float* W_lift = (const float*)d_in[2];
    const float* b_lift = (const float*)d_in[3];
    const float* W1     = (const float*)d_in[4];
    const float* b1     = (const float*)d_in[5];
    const float* W2     = (const float*)d_in[6];
    const float* b2     = (const float*)d_in[7];
    const float* W_ro   = (const float*)d_in[8];
    const float* b_ro   = (const float*)d_in[9];
    float* out = (float*)d_out;

    const size_t smem_bytes = SMEM_FLOATS * sizeof(float);
    cudaFuncSetAttribute(gnn_fused_kernel,
                         cudaFuncAttributeMaxDynamicSharedMemorySize,
                         (int)smem_bytes);

    const int batch = 16384;
    gnn_fused_kernel<<<batch / GROUPS, THREADS, smem_bytes>>>(
        x, adj, W_lift, b_lift, W1, b1, W2, b2, W_ro, b_ro, out);
}

// round 10
// speedup vs baseline: 1.2872x; 1.0268x over previous
#include <cuda_runtime.h>

// GNNSurrogate fully fused, r=2 node blocking, swizzled local tile.
// 512 threads/block = 8 samples x 64 threads; each thread owns node rows
// i and i+64 of its sample.
// - local tile rows stride 32 floats with 16B-chunk XOR swizzle (q ^ (row&7)):
//   STS.128 conflict-free (was 32-way), broadcast reads unchanged.
// - 16 warps/SM (occ 25%) to push the L1/LDS crossbar toward saturation.

#define THREADS 512
#define GROUPS 8

// shared-memory float offsets
#define ADJ_OFF 0
#define ADJ_SZ  (128 * 129)          // padded stride 129: conflict-free column reads
#define WL_OFF  (ADJ_OFF + ADJ_SZ)
#define BL_OFF  (WL_OFF + 96)
#define W1_OFF  (BL_OFF + 32)
#define B1_OFF  (W1_OFF + 3072)
#define B2_OFF  (W2_OFF + 3072)
#define W2_OFF  (B1_OFF + 96)
#define WRO_OFF (B2_OFF + 96)
#define RED_OFF (WRO_OFF + 32)       // 16 floats (per-warp partials)
#define LOC_OFF (RED_OFF + 16)       // 23024 floats -> 92096 B, 16B aligned
#define SMEM_FLOATS (LOC_OFF + GROUPS * 128 * 32)   // 55792 floats = 223168 B

typedef unsigned long long u64;

__device__ __forceinline__ u64 f2pack(float lo, float hi) {
    u64 r;
    asm("mov.b64 %0, {%1, %2};" : "=l"(r) : "f"(lo), "f"(hi));
    return r;
}
__device__ __forceinline__ void f2unpack(u64 v, float& lo, float& hi) {
    asm("mov.b64 {%0, %1}, %2;" : "=f"(lo), "=f"(hi) : "l"(v));
}
__device__ __forceinline__ u64 ffma2(u64 a, u64 b, u64 c) {
    u64 d;
    asm("fma.rn.f32x2 %0, %1, %2, %3;" : "=l"(d) : "l"(a), "l"(b), "l"(c));
    return d;
}

// one 32->32 matmul step applied to two rows, weights broadcast from smem
__device__ __forceinline__ void mm2(const float* __restrict__ wbase,
                                    const float* __restrict__ bias,
                                    const float* ha, const float* hb,
                                    u64* ta, u64* tb)
{
    const u64* bp = (const u64*)bias;
    #pragma unroll
    for (int q = 0; q < 16; q++) { ta[q] = bp[q]; tb[q] = bp[q]; }
    const ulonglong2* w = (const ulonglong2*)wbase;
    #pragma unroll 4
    for (int k = 0; k < 32; k++) {
        u64 ak = f2pack(ha[k], ha[k]);
        u64 bk = f2pack(hb[k], hb[k]);
        #pragma unroll
        for (int q = 0; q < 8; q++) {
            ulonglong2 p = w[k * 8 + q];
            ta[2 * q]     = ffma2(ak, p.x, ta[2 * q]);
            ta[2 * q + 1] = ffma2(ak, p.y, ta[2 * q + 1]);
            tb[2 * q]     = ffma2(bk, p.x, tb[2 * q]);
            tb[2 * q + 1] = ffma2(bk, p.y, tb[2 * q + 1]);
        }
    }
}

__global__ void __launch_bounds__(THREADS, 1) gnn_fused_kernel(
    const float* __restrict__ x, const float* __restrict__ adj,
    const float* __restrict__ W_lift, const float* __restrict__ b_lift,
    const float* __restrict__ W1, const float* __restrict__ b1,
    const float* __restrict__ W2, const float* __restrict__ b2,
    const float* __restrict__ W_ro, const float* __restrict__ b_ro,
    float* __restrict__ out)
{
    extern __shared__ float sm[];
    const int tid = threadIdx.x;

    // ---- stage adjacency (padded) + weights ----
    for (int idx = tid; idx < 128 * 128; idx += THREADS)
        sm[ADJ_OFF + (idx >> 7) * 129 + (idx & 127)] = adj[idx];
    for (int idx = tid; idx < 96; idx += THREADS)   sm[WL_OFF + idx] = W_lift[idx];
    if (tid < 32)                                   sm[BL_OFF + tid] = b_lift[tid];
    for (int idx = tid; idx < 3072; idx += THREADS) sm[W1_OFF + idx] = W1[idx];
    for (int idx = tid; idx < 96; idx += THREADS)   sm[B1_OFF + idx] = b1[idx];
    for (int idx = tid; idx < 3072; idx += THREADS) sm[W2_OFF + idx] = W2[idx];
    for (int idx = tid; idx < 96; idx += THREADS)   sm[B2_OFF + idx] = b2[idx];
    if (tid < 32)                                   sm[WRO_OFF + tid] = W_ro[tid];
    __syncthreads();

    const int g  = tid >> 6;          // sample group 0..7
    const int i0 = tid & 63;          // first node row
    const int i1 = i0 + 64;           // second node row
    const int b  = blockIdx.x * GROUPS + g;

    // ---- lift for both rows ----
    float ha[32], hb[32];
    {
        const float* xa = x + ((size_t)b * 128 + i0) * 3;
        const float* xb = x + ((size_t)b * 128 + i1) * 3;
        float a0 = xa[0], a1 = xa[1], a2 = xa[2];
        float c0 = xb[0], c1 = xb[1], c2 = xb[2];
        #pragma unroll
        for (int j = 0; j < 32; j++) {
            float w0 = sm[WL_OFF + j], w1v = sm[WL_OFF + 32 + j],
                  w2v = sm[WL_OFF + 64 + j], bl = sm[BL_OFF + j];
            ha[j] = fmaf(a0, w0, fmaf(a1, w1v, fmaf(a2, w2v, bl)));
            hb[j] = fmaf(c0, w0, fmaf(c1, w1v, fmaf(c2, w2v, bl)));
        }
    }

    float* loc = sm + LOC_OFF + g * 4096;
    const int swa = i0 & 7;           // swizzle keys for this thread's rows
    const int swb = i1 & 7;           // (i1 = i0+64 -> same low bits, kept explicit)

    for (int l = 0; l < 3; l++) {
        // ---- matmul1 + relu ----
        u64 ta[16], tb[16];
        mm2(sm + W1_OFF + l * 1024, sm + B1_OFF + l * 32, ha, hb, ta, tb);
        #pragma unroll
        for (int q = 0; q < 16; q++) {
            float lo, hi;
            f2unpack(ta[q], lo, hi);
            ha[2 * q] = fmaxf(lo, 0.f); ha[2 * q + 1] = fmaxf(hi, 0.f);
            f2unpack(tb[q], lo, hi);
            hb[2 * q] = fmaxf(lo, 0.f); hb[2 * q + 1] = fmaxf(hi, 0.f);
        }

        // ---- matmul2 ----
        u64 va[16], vb[16];
        mm2(sm + W2_OFF + l * 1024, sm + B2_OFF + l * 32, ha, hb, va, vb);

        // ---- write local rows (swizzled, conflict-free STS.128) ----
        {
            float* ra = loc + i0 * 32;
            float* rb = loc + i1 * 32;
            #pragma unroll
            for (int q = 0; q < 8; q++) {
                ulonglong2 pa; pa.x = va[2 * q]; pa.y = va[2 * q + 1];
                ulonglong2 pb; pb.x = vb[2 * q]; pb.y = vb[2 * q + 1];
                *(ulonglong2*)(ra + ((q ^ swa) << 2)) = pa;
                *(ulonglong2*)(rb + ((q ^ swb) << 2)) = pb;
            }
        }
        __syncthreads();

        // ---- aggregation: both rows share each local[j] broadcast load ----
        u64 aa[16], ab[16];
        #pragma unroll
        for (int q = 0; q < 16; q++) { aa[q] = 0ULL; ab[q] = 0ULL; }
        const float* arowa = sm + ADJ_OFF + i0 * 129;
        const float* arowb = sm + ADJ_OFF + i1 * 129;
        #pragma unroll 2
        for (int j = 0; j < 128; j++) {
            u64 ca = f2pack(arowa[j], arowa[j]);
            u64 cb = f2pack(arowb[j], arowb[j]);
            const float* Lrow = loc + j * 32;
            const int swj = j & 7;
            #pragma unroll
            for (int q = 0; q < 8; q++) {
                ulonglong2 p = *(const ulonglong2*)(Lrow + ((q ^ swj) << 2));
                aa[2 * q]     = ffma2(ca, p.x, aa[2 * q]);
                aa[2 * q + 1] = ffma2(ca, p.y, aa[2 * q + 1]);
                ab[2 * q]     = ffma2(cb, p.x, ab[2 * q]);
                ab[2 * q + 1] = ffma2(cb, p.y, ab[2 * q + 1]);
            }
        }
        #pragma unroll
        for (int q = 0; q < 16; q++) {
            f2unpack(aa[q], ha[2 * q], ha[2 * q + 1]);
            f2unpack(ab[q], hb[2 * q], hb[2 * q + 1]);
        }
        __syncthreads();   // protect local tile before next layer's writes
    }

    // ---- readout ----
    float s = 0.f;
    #pragma unroll
    for (int c = 0; c < 32; c++) {
        float w = sm[WRO_OFF + c];
        s = fmaf(ha[c], w, s);
        s = fmaf(hb[c], w, s);
    }
    #pragma unroll
    for (int o = 16; o > 0; o >>= 1) s += __shfl_xor_sync(0xffffffffu, s, o);
    const int w = tid >> 5;
    if ((tid & 31) == 0) sm[RED_OFF + w] = s;
    __syncthreads();
    if (i0 == 0) {
        float tot = sm[RED_OFF + 2 * g] + sm[RED_OFF + 2 * g + 1];
        out[b] = fmaf(tot, 1.f / 128.f, b_ro[0]);
    }
}

extern "C" void kernel_launch(void* const* d_in, const int* in_sizes, int n_in,
                              void* d_out, int out_size)
{
    const float* x      = (const float*)d_in[0];
    const float* adj    = (const float*)d_in[1];
    const float* W_lift = (const float*)d_in[2];
    const float* b_lift = (const float*)d_in[3];
    const float* W1     = (const float*)d_in[4];
    const float* b1     = (const float*)d_in[5];
    const float* W2     = (const float*)d_in[6];
    const float* b2     = (const float*)d_in[7];
    const float* W_ro   = (const float*)d_in[8];
    const float* b_ro   = (const float*)d_in[9];
    float* out = (float*)d_out;

    const size_t smem_bytes = SMEM_FLOATS * sizeof(float);
    cudaFuncSetAttribute(gnn_fused_kernel,
                         cudaFuncAttributeMaxDynamicSharedMemorySize,
                         (int)smem_bytes);

    const int batch = 16384;
    gnn_fused_kernel<<<batch / GROUPS, THREADS, smem_bytes>>>(
        x, adj, W_lift, b_lift, W1, b1, W2, b2, W_ro, b_ro, out);
}